// round 5
// baseline (speedup 1.0000x reference)
#include <cuda_runtime.h>
#include <math.h>
#include <stdint.h>
#include <stddef.h>

#define BB   32
#define NN   196
#define TT   128
#define DIMG 768
#define DH   512
#define VV   10000

#define NCTA 148
#define NTHR 256

// ---------------- scratch (device globals; no allocation allowed) ----------
__device__ float g_keys[BB * NN * DH];       // 12.8 MB
__device__ float g_Wk[BB * NN * DH];         // 12.8 MB
__device__ float g_Xemb[BB * TT * DH];       // 8.4 MB  emb[tgt]
__device__ float g_X[BB * TT * 4 * DH];      // 33.5 MB  x_t @ W_ih[:, :512]^T
__device__ float g_H[BB * TT * DH];          // 8.4 MB  all h_new
__device__ float g_h[BB * DH];
__device__ float g_c[BB * DH];
__device__ float g_hwh_p[8 * BB * DH];       // hWh partials (8 k-slots)
__device__ float g_sc[BB * 256];             // scores (196 used, pitch 256)
__device__ float g_ctx[BB * DH];
__device__ float g_pg[4 * BB * 4 * DH];      // gate partials (4 k-slots of 256)

__device__ volatile unsigned g_bar_epoch;
__device__ unsigned g_bar_cnt;

// ---------------- FMA-only tanh (no MUFU!) ----------------------------------
// Eigen-style rational tanh: t*P(t^2)/Q(t^2), |t| clamped to 7.905.
// Reciprocal via bit-trick seed + 3 Newton steps (FMA pipe only).
// Max error ~1e-6. MUFU throughput on B300 is only 0.5 op/cyc/SM, so the
// 3.2M tanh/step MUST stay off MUFU.
__device__ __forceinline__ float tanh_fma(float x) {
    float t = fminf(fmaxf(x, -7.90531110763549805f), 7.90531110763549805f);
    float x2 = t * t;
    float p = -2.76076847742355e-16f;
    p = fmaf(p, x2,  2.00018790482477e-13f);
    p = fmaf(p, x2, -8.60467152213735e-11f);
    p = fmaf(p, x2,  5.12229709037114e-08f);
    p = fmaf(p, x2,  1.48572235717979e-05f);
    p = fmaf(p, x2,  6.37261928875436e-04f);
    p = fmaf(p, x2,  4.89352455891786e-03f);
    p = p * t;
    float q = 1.19825839466702e-06f;
    q = fmaf(q, x2, 1.18534705686654e-04f);
    q = fmaf(q, x2, 2.26843463243900e-03f);
    q = fmaf(q, x2, 4.89352518554385e-03f);
    // fast reciprocal of q (q > 0 always)
    float r = __uint_as_float(0x7EF311C3u - __float_as_uint(q));
    r = r * fmaf(-q, r, 2.0f);
    r = r * fmaf(-q, r, 2.0f);
    r = r * fmaf(-q, r, 2.0f);
    return p * r;
}
__device__ __forceinline__ float sigmoidf_acc(float x) {
    return 1.0f / (1.0f + expf(-x));   // rare (49k/step) — MUFU ok here
}
__device__ __forceinline__ float warp_sum(float v) {
#pragma unroll
    for (int o = 16; o > 0; o >>= 1) v += __shfl_xor_sync(0xffffffffu, v, o);
    return v;
}
__device__ __forceinline__ float warp_max(float v) {
#pragma unroll
    for (int o = 16; o > 0; o >>= 1) v = fmaxf(v, __shfl_xor_sync(0xffffffffu, v, o));
    return v;
}
__device__ __forceinline__ float block_sum256(float v, float* red) {
    int w = threadIdx.x >> 5, l = threadIdx.x & 31;
    v = warp_sum(v);
    if (l == 0) red[w] = v;
    __syncthreads();
    float r = red[0] + red[1] + red[2] + red[3] + red[4] + red[5] + red[6] + red[7];
    __syncthreads();
    return r;
}
__device__ __forceinline__ float block_max256(float v, float* red) {
    int w = threadIdx.x >> 5, l = threadIdx.x & 31;
    v = warp_max(v);
    if (l == 0) red[w] = v;
    __syncthreads();
    float r = red[0];
#pragma unroll
    for (int i = 1; i < 8; i++) r = fmaxf(r, red[i]);
    __syncthreads();
    return r;
}

// grid-wide barrier (all NCTA CTAs resident)
__device__ __forceinline__ void grid_barrier() {
    __threadfence();
    __syncthreads();
    if (threadIdx.x == 0) {
        unsigned e = g_bar_epoch;
        if (atomicAdd(&g_bar_cnt, 1u) == NCTA - 1) {
            g_bar_cnt = 0;
            __threadfence();
            g_bar_epoch = e + 1;
        } else {
            while (g_bar_epoch == e) { __nanosleep(32); }
        }
    }
    __syncthreads();
    __threadfence();
}

// ---------------- generic tiled fp32 GEMM: C = A(MxK,lda) * B(NxK,ldb)^T ----
__global__ __launch_bounds__(256) void sgemm_nt(
    const float* __restrict__ A, int lda,
    const float* __restrict__ Bm, int ldb,
    const float* __restrict__ bias, float* __restrict__ C, int ldc,
    int M, int Nc, int K)
{
    __shared__ float As[8][128];
    __shared__ float Bs[8][128];
    int bm = blockIdx.y * 128, bn = blockIdx.x * 128;
    int tid = threadIdx.x;
    int tx = (tid & 15) * 8;
    int ty = (tid >> 4) * 8;

    float acc[8][8];
#pragma unroll
    for (int i = 0; i < 8; i++)
#pragma unroll
        for (int j = 0; j < 8; j++) acc[i][j] = 0.0f;

    for (int k0 = 0; k0 < K; k0 += 8) {
#pragma unroll
        for (int i = tid; i < 1024; i += 256) {
            int m = i >> 3, k = i & 7;
            int gm = bm + m;
            As[k][m] = (gm < M) ? A[(size_t)gm * lda + k0 + k] : 0.0f;
        }
#pragma unroll
        for (int i = tid; i < 1024; i += 256) {
            int n = i >> 3, k = i & 7;
            int gn = bn + n;
            Bs[k][n] = (gn < Nc) ? Bm[(size_t)gn * ldb + k0 + k] : 0.0f;
        }
        __syncthreads();
#pragma unroll
        for (int k = 0; k < 8; k++) {
            float4 a0 = *reinterpret_cast<const float4*>(&As[k][ty]);
            float4 a1 = *reinterpret_cast<const float4*>(&As[k][ty + 4]);
            float4 b0 = *reinterpret_cast<const float4*>(&Bs[k][tx]);
            float4 b1 = *reinterpret_cast<const float4*>(&Bs[k][tx + 4]);
            float av[8] = {a0.x, a0.y, a0.z, a0.w, a1.x, a1.y, a1.z, a1.w};
            float bv[8] = {b0.x, b0.y, b0.z, b0.w, b1.x, b1.y, b1.z, b1.w};
#pragma unroll
            for (int i = 0; i < 8; i++)
#pragma unroll
                for (int j = 0; j < 8; j++)
                    acc[i][j] = fmaf(av[i], bv[j], acc[i][j]);
        }
        __syncthreads();
    }
#pragma unroll
    for (int i = 0; i < 8; i++) {
        int gm = bm + ty + i;
        if (gm >= M) continue;
#pragma unroll
        for (int j = 0; j < 8; j++) {
            int gn = bn + tx + j;
            if (gn < Nc)
                C[(size_t)gm * ldc + gn] = acc[i][j] + (bias ? bias[gn] : 0.0f);
        }
    }
}

// ---------------- embedding gather ------------------------------------------
__global__ __launch_bounds__(256) void gather_emb(
    const int* __restrict__ tgt, const float* __restrict__ emb)
{
    int idx = blockIdx.x * 256 + threadIdx.x;
    if (idx >= BB * TT * DH) return;
    int row = idx >> 9;
    int d = idx & 511;
    g_Xemb[idx] = emb[(size_t)tgt[row] * DH + d];
}

// ---------------- skinny 32xK chunk: acc += A(32x64) * B(64x64)^T ----------
__device__ __forceinline__ void skinny_chunk(
    const float* __restrict__ A, int lda,
    const float* __restrict__ B, int ldb,
    float acc[8], float* sA, float* sB)
{
    int tid = threadIdx.x;
    __syncthreads();
#pragma unroll
    for (int i = tid; i < 32 * 64; i += 256) {
        int b = i >> 6, k = i & 63;
        sA[k * 36 + b] = A[(size_t)b * lda + k];
    }
#pragma unroll
    for (int i = tid; i < 64 * 64; i += 256) {
        int n = i >> 6, k = i & 63;
        sB[k * 65 + n] = B[(size_t)n * ldb + k];
    }
    __syncthreads();
    int nl = tid & 63, bq = tid >> 6;
#pragma unroll 8
    for (int k = 0; k < 64; k++) {
        float w = sB[k * 65 + nl];
        const float4* ap = reinterpret_cast<const float4*>(&sA[k * 36 + bq * 8]);
        float4 a0 = ap[0], a1 = ap[1];
        acc[0] = fmaf(a0.x, w, acc[0]); acc[1] = fmaf(a0.y, w, acc[1]);
        acc[2] = fmaf(a0.z, w, acc[2]); acc[3] = fmaf(a0.w, w, acc[3]);
        acc[4] = fmaf(a1.x, w, acc[4]); acc[5] = fmaf(a1.y, w, acc[5]);
        acc[6] = fmaf(a1.z, w, acc[6]); acc[7] = fmaf(a1.w, w, acc[7]);
    }
}

// ---------------- persistent recurrence kernel ------------------------------
__global__ __launch_bounds__(NTHR) void recurrence(
    const float* __restrict__ cls,
    const float* __restrict__ ih_W, const float* __restrict__ ih_b,
    const float* __restrict__ ic_W, const float* __restrict__ ic_b,
    const float* __restrict__ attn_Wh, const float* __restrict__ attn_v,
    const float* __restrict__ W_ih, const float* __restrict__ W_hh,
    const float* __restrict__ b_ih, const float* __restrict__ b_hh,
    const float* __restrict__ lnw, const float* __restrict__ lnb)
{
    __shared__ float sh[64 * 36 + 64 * 65];   // 25.9 KB, aliased per phase
    float* sA = sh;
    float* sB = sh + 64 * 36;
    int tid = threadIdx.x;
    int cta = blockIdx.x;
    int nl = tid & 63, bq = tid >> 6;

    // ---- prologue: h0 / c0 ---------------------------------------------------
    for (int task = cta; task < 16; task += NCTA) {
        int mat = task >> 3;
        int n0 = (task & 7) * 64;
        const float* W = mat ? ic_W : ih_W;
        const float* bias = mat ? ic_b : ih_b;
        float* dst = mat ? g_c : g_h;
        float acc[8] = {0, 0, 0, 0, 0, 0, 0, 0};
        for (int kc = 0; kc < 12; kc++)
            skinny_chunk(cls + kc * 64, DIMG, W + (size_t)n0 * DIMG + kc * 64, DIMG,
                         acc, sA, sB);
        float bv = bias[n0 + nl];
#pragma unroll
        for (int j = 0; j < 8; j++)
            dst[(size_t)(bq * 8 + j) * DH + n0 + nl] = acc[j] + bv;
    }
    grid_barrier();

    // ---- time loop ------------------------------------------------------------
    for (int t = 0; t < TT; t++) {
        // P1: hWh partials = h @ attn_Wh^T  (64 tasks)
        for (int task = cta; task < 64; task += NCTA) {
            int kslot = task >> 3, n0 = (task & 7) * 64, k0 = kslot * 64;
            float acc[8] = {0, 0, 0, 0, 0, 0, 0, 0};
            skinny_chunk(g_h + k0, DH, attn_Wh + (size_t)n0 * DH + k0, DH,
                         acc, sA, sB);
#pragma unroll
            for (int j = 0; j < 8; j++)
                g_hwh_p[((size_t)kslot * BB + bq * 8 + j) * DH + n0 + nl] = acc[j];
        }
        grid_barrier();

        // P2: scores  (32 b x 4 chunks of 49 n = 128 tasks) — FMA-only tanh
        {
            float* hwh = sh;          // 512
            float* vsm = sh + 512;    // 512
            for (int task = cta; task < 128; task += NCTA) {
                int b = task >> 2, n0 = (task & 3) * 49;
                __syncthreads();
#pragma unroll
                for (int d = tid; d < DH; d += 256) {
                    float s = 0.0f;
#pragma unroll
                    for (int s8 = 0; s8 < 8; s8++)
                        s += g_hwh_p[((size_t)s8 * BB + b) * DH + d];
                    hwh[d] = s;
                    vsm[d] = attn_v[d];
                }
                __syncthreads();
                int w = tid >> 5, l = tid & 31;
                for (int n = n0 + w; n < n0 + 49; n += 8) {
                    const float* wk = &g_Wk[((size_t)b * NN + n) * DH];
                    float e = 0.0f;
#pragma unroll 4
                    for (int k = l; k < DH; k += 32)
                        e = fmaf(tanh_fma(hwh[k] + wk[k]), vsm[k], e);
                    e = warp_sum(e);
                    if (l == 0) g_sc[b * 256 + n] = e;
                }
            }
        }
        grid_barrier();

        // P3: softmax + ctx  (64 tasks)
        {
            float* alpha = sh;        // 256
            float* red = sh + 256;    // 8
            for (int task = cta; task < 64; task += NCTA) {
                int b = task >> 1, d0 = (task & 1) * 256;
                __syncthreads();
                float s = (tid < NN) ? g_sc[b * 256 + tid] : -1e30f;
                float m = block_max256(s, red);
                float ex = (tid < NN) ? expf(s - m) : 0.0f;
                alpha[tid] = ex;
                float ssum = block_sum256(ex, red);
                float inv = 1.0f / ssum;
                int d = d0 + tid;
                float ctx = 0.0f;
                const float* kb = &g_keys[(size_t)b * NN * DH + d];
#pragma unroll 4
                for (int n = 0; n < NN; n++)
                    ctx = fmaf(alpha[n], kb[(size_t)n * DH], ctx);
                g_ctx[b * DH + d] = ctx * inv;
            }
        }
        grid_barrier();

        // P4: gate partials (128 tasks)
        for (int task = cta; task < 128; task += NCTA) {
            int kslot = task >> 5, n0 = (task & 31) * 64, k0 = kslot * 256;
            float acc[8] = {0, 0, 0, 0, 0, 0, 0, 0};
            for (int kc = 0; kc < 4; kc++) {
                int kk = k0 + kc * 64;
                if (kk < 512)
                    skinny_chunk(g_ctx + kk, DH,
                                 W_ih + (size_t)n0 * (2 * DH) + DH + kk, 2 * DH,
                                 acc, sA, sB);
                else
                    skinny_chunk(g_h + (kk - 512), DH,
                                 W_hh + (size_t)n0 * DH + (kk - 512), DH,
                                 acc, sA, sB);
            }
#pragma unroll
            for (int j = 0; j < 8; j++)
                g_pg[((size_t)kslot * BB + bq * 8 + j) * (4 * DH) + n0 + nl] = acc[j];
        }
        grid_barrier();

        // P5: cell + layernorm  (32 tasks)
        {
            float* red = sh;
            for (int task = cta; task < BB; task += NCTA) {
                int b = task;
                size_t xrow = ((size_t)b * TT + t) * (4 * DH);
                float hr[2], cn[2];
#pragma unroll
                for (int half = 0; half < 2; half++) {
                    int d = tid + half * 256;
                    float gi = 0.f, gf = 0.f, gg = 0.f, go = 0.f;
#pragma unroll
                    for (int s = 0; s < 4; s++) {
                        const float* p = g_pg + ((size_t)s * BB + b) * (4 * DH);
                        gi += p[d]; gf += p[DH + d];
                        gg += p[2 * DH + d]; go += p[3 * DH + d];
                    }
                    const float* xp = g_X + xrow;
                    gi += xp[d] + b_ih[d] + b_hh[d];
                    gf += xp[DH + d] + b_ih[DH + d] + b_hh[DH + d];
                    gg += xp[2 * DH + d] + b_ih[2 * DH + d] + b_hh[2 * DH + d];
                    go += xp[3 * DH + d] + b_ih[3 * DH + d] + b_hh[3 * DH + d];
                    float c = g_c[b * DH + d];
                    cn[half] = sigmoidf_acc(gf) * c + sigmoidf_acc(gi) * tanh_fma(gg);
                    hr[half] = sigmoidf_acc(go) * tanh_fma(cn[half]);
                }
                __syncthreads();
                float mu = block_sum256(hr[0] + hr[1], red) * (1.0f / DH);
                float va = block_sum256(hr[0] * hr[0] + hr[1] * hr[1], red) * (1.0f / DH)
                           - mu * mu;
                float rstd = rsqrtf(va + 1e-5f);
#pragma unroll
                for (int half = 0; half < 2; half++) {
                    int d = tid + half * 256;
                    float hn = (hr[half] - mu) * rstd * lnw[d] + lnb[d];
                    g_c[b * DH + d] = cn[half];
                    g_h[b * DH + d] = hn;
                    g_H[((size_t)b * TT + t) * DH + d] = hn;
                }
            }
        }
        grid_barrier();
    }
}

// ---------------- launcher ---------------------------------------------------
extern "C" void kernel_launch(void* const* d_in, const int* in_sizes, int n_in,
                              void* d_out, int out_size)
{
    (void)in_sizes; (void)n_in; (void)out_size;
    const float* patches = (const float*)d_in[0];
    const float* cls     = (const float*)d_in[1];
    const int*   tgt     = (const int*)  d_in[2];
    const float* emb     = (const float*)d_in[3];
    const float* kv_W    = (const float*)d_in[4];
    const float* kv_b    = (const float*)d_in[5];
    const float* ih_W    = (const float*)d_in[6];
    const float* ih_b    = (const float*)d_in[7];
    const float* ic_W    = (const float*)d_in[8];
    const float* ic_b    = (const float*)d_in[9];
    const float* attn_Wh = (const float*)d_in[10];
    const float* attn_Wk = (const float*)d_in[11];
    const float* attn_v  = (const float*)d_in[12];
    const float* W_ih    = (const float*)d_in[13];
    const float* W_hh    = (const float*)d_in[14];
    const float* b_ih    = (const float*)d_in[15];
    const float* b_hh    = (const float*)d_in[16];
    const float* ln_w    = (const float*)d_in[17];
    const float* ln_b    = (const float*)d_in[18];
    const float* out_W   = (const float*)d_in[19];
    const float* out_b   = (const float*)d_in[20];
    float* out = (float*)d_out;

    float *p_keys, *p_Wk, *p_Xemb, *p_X, *p_H;
    cudaGetSymbolAddress((void**)&p_keys, g_keys);
    cudaGetSymbolAddress((void**)&p_Wk,   g_Wk);
    cudaGetSymbolAddress((void**)&p_Xemb, g_Xemb);
    cudaGetSymbolAddress((void**)&p_X,    g_X);
    cudaGetSymbolAddress((void**)&p_H,    g_H);

    // ---- precompute ----
    sgemm_nt<<<dim3(DH / 128, (BB * NN) / 128), 256>>>(
        patches, DIMG, kv_W, DIMG, kv_b, p_keys, DH, BB * NN, DH, DIMG);
    sgemm_nt<<<dim3(DH / 128, (BB * NN) / 128), 256>>>(
        p_keys, DH, attn_Wk, DH, nullptr, p_Wk, DH, BB * NN, DH, DH);
    gather_emb<<<(BB * TT * DH + 255) / 256, 256>>>(tgt, emb);
    sgemm_nt<<<dim3((4 * DH) / 128, (BB * TT) / 128), 256>>>(
        p_Xemb, DH, W_ih, 2 * DH, nullptr, p_X, 4 * DH, BB * TT, 4 * DH, DH);

    // ---- persistent recurrence ----
    recurrence<<<NCTA, NTHR>>>(cls, ih_W, ih_b, ic_W, ic_b,
                               attn_Wh, attn_v, W_ih, W_hh, b_ih, b_hh,
                               ln_w, ln_b);

    // ---- deferred logits ----
    sgemm_nt<<<dim3((VV + 127) / 128, (BB * TT) / 128), 256>>>(
        p_H, DH, out_W, DH, out_b, out, VV, BB * TT, VV, DH);
}

// round 7
// speedup vs baseline: 1.1916x; 1.1916x over previous
#include <cuda_runtime.h>
#include <cuda_bf16.h>
#include <math.h>
#include <stdint.h>
#include <stddef.h>

#define BB   32
#define NN   196
#define TT   128
#define DIMG 768
#define DH   512
#define VV   10000
#define VPAD 10240            // 40 * 256

#define NCTA 148
#define NTHR 256

// ============================ scratch (device globals) =======================
__device__ float g_keys[BB * NN * DH];
__device__ float g_Wk[BB * NN * DH];
__device__ float g_X[BB * TT * 4 * DH];
__device__ float g_H[BB * TT * DH];
__device__ float g_h[BB * DH];
__device__ float g_c[BB * DH];
__device__ float g_hwh_p[8 * BB * DH];
__device__ float g_sc[BB * 256];
__device__ float g_ctx[BB * DH];
__device__ float g_pg[4 * BB * 4 * DH];

// bf16 3-segment split buffers. Zero-initialized; rows [VV, VPAD) of s_outW2
// are never written and stay zero.
__device__ __nv_bfloat16 s_patches2[BB * NN * 3 * DIMG];
__device__ __nv_bfloat16 s_kvW2[DH * 3 * DIMG];
__device__ __nv_bfloat16 s_keys2[BB * NN * 3 * DH];
__device__ __nv_bfloat16 s_attnWk2[DH * 3 * DH];
__device__ __nv_bfloat16 s_Xemb2[BB * TT * 3 * DH];
__device__ __nv_bfloat16 s_Wih2[(4 * DH) * 3 * DH];
__device__ __nv_bfloat16 s_H2[BB * TT * 3 * DH];
__device__ __nv_bfloat16 s_outW2[VPAD * 3 * DH];

// hierarchical grid barrier state
__device__ unsigned g_cnt_grp[32];
__device__ unsigned g_cnt_root;
__device__ volatile unsigned g_epoch;

// ============================ small helpers ==================================
__device__ __forceinline__ uint32_t smem_u32(const void* p) {
    uint32_t a;
    asm("{ .reg .u64 t; cvta.to.shared.u64 t, %1; cvt.u32.u64 %0, t; }"
        : "=r"(a) : "l"(p));
    return a;
}
__device__ __forceinline__ void ldsm_x4(uint32_t& r0, uint32_t& r1,
                                        uint32_t& r2, uint32_t& r3,
                                        uint32_t addr) {
    asm volatile("ldmatrix.sync.aligned.m8n8.x4.shared.b16 {%0,%1,%2,%3}, [%4];"
                 : "=r"(r0), "=r"(r1), "=r"(r2), "=r"(r3) : "r"(addr));
}
__device__ __forceinline__ void ldsm_x2(uint32_t& r0, uint32_t& r1,
                                        uint32_t addr) {
    asm volatile("ldmatrix.sync.aligned.m8n8.x2.shared.b16 {%0,%1}, [%2];"
                 : "=r"(r0), "=r"(r1) : "r"(addr));
}
__device__ __forceinline__ void mma16816(float* c, const uint32_t* a,
                                         const uint32_t* b) {
    asm volatile(
        "mma.sync.aligned.m16n8k16.row.col.f32.bf16.bf16.f32 "
        "{%0,%1,%2,%3}, {%4,%5,%6,%7}, {%8,%9}, {%0,%1,%2,%3};"
        : "+f"(c[0]), "+f"(c[1]), "+f"(c[2]), "+f"(c[3])
        : "r"(a[0]), "r"(a[1]), "r"(a[2]), "r"(a[3]), "r"(b[0]), "r"(b[1]));
}

__device__ __forceinline__ float tanh_fma(float x) {
    float t = fminf(fmaxf(x, -7.90531110763549805f), 7.90531110763549805f);
    float x2 = t * t;
    float p = -2.76076847742355e-16f;
    p = fmaf(p, x2,  2.00018790482477e-13f);
    p = fmaf(p, x2, -8.60467152213735e-11f);
    p = fmaf(p, x2,  5.12229709037114e-08f);
    p = fmaf(p, x2,  1.48572235717979e-05f);
    p = fmaf(p, x2,  6.37261928875436e-04f);
    p = fmaf(p, x2,  4.89352455891786e-03f);
    p = p * t;
    float q = 1.19825839466702e-06f;
    q = fmaf(q, x2, 1.18534705686654e-04f);
    q = fmaf(q, x2, 2.26843463243900e-03f);
    q = fmaf(q, x2, 4.89352518554385e-03f);
    float r = __uint_as_float(0x7EF311C3u - __float_as_uint(q));
    r = r * fmaf(-q, r, 2.0f);
    r = r * fmaf(-q, r, 2.0f);
    r = r * fmaf(-q, r, 2.0f);
    return p * r;
}
__device__ __forceinline__ float sigmoidf_acc(float x) {
    return 1.0f / (1.0f + expf(-x));
}
__device__ __forceinline__ float warp_sum(float v) {
#pragma unroll
    for (int o = 16; o > 0; o >>= 1) v += __shfl_xor_sync(0xffffffffu, v, o);
    return v;
}
__device__ __forceinline__ float warp_max(float v) {
#pragma unroll
    for (int o = 16; o > 0; o >>= 1) v = fmaxf(v, __shfl_xor_sync(0xffffffffu, v, o));
    return v;
}
__device__ __forceinline__ float block_sum256(float v, float* red) {
    int w = threadIdx.x >> 5, l = threadIdx.x & 31;
    v = warp_sum(v);
    if (l == 0) red[w] = v;
    __syncthreads();
    float r = red[0] + red[1] + red[2] + red[3] + red[4] + red[5] + red[6] + red[7];
    __syncthreads();
    return r;
}
__device__ __forceinline__ float block_max256(float v, float* red) {
    int w = threadIdx.x >> 5, l = threadIdx.x & 31;
    v = warp_max(v);
    if (l == 0) red[w] = v;
    __syncthreads();
    float r = red[0];
#pragma unroll
    for (int i = 1; i < 8; i++) r = fmaxf(r, red[i]);
    __syncthreads();
    return r;
}

// hierarchical grid barrier: 8-CTA groups -> root; tid0-only acquire fence
#define NGRP ((NCTA + 7) / 8)
__device__ __forceinline__ void grid_barrier() {
    __threadfence();               // release (per-thread; cheap, stores drained)
    __syncthreads();
    if (threadIdx.x == 0) {
        unsigned e = g_epoch;
        unsigned g = (unsigned)blockIdx.x >> 3;
        unsigned gsz = (g == NGRP - 1) ? (NCTA - g * 8) : 8u;
        if (atomicAdd(&g_cnt_grp[g], 1u) == gsz - 1) {
            atomicExch(&g_cnt_grp[g], 0u);
            __threadfence();
            if (atomicAdd(&g_cnt_root, 1u) == NGRP - 1) {
                atomicExch(&g_cnt_root, 0u);
                __threadfence();
                g_epoch = e + 1;
            } else {
                while (g_epoch == e) { }
            }
        } else {
            while (g_epoch == e) { }
        }
        __threadfence();           // acquire: invalidate this SM's L1
    }
    __syncthreads();
}

// ============================ split helpers ==================================
// A-mode (modeB=0): [hi | lo | hi] ; B-mode (modeB=1): [hi | hi | lo]
__device__ __forceinline__ void split_one(float x, __nv_bfloat16* dst,
                                          size_t base, int K, int k, int modeB) {
    __nv_bfloat16 hi = __float2bfloat16(x);
    __nv_bfloat16 lo = __float2bfloat16(x - __bfloat162float(hi));
    dst[base + k] = hi;
    dst[base + K + k] = modeB ? hi : lo;
    dst[base + 2 * K + k] = modeB ? lo : hi;
}

__global__ __launch_bounds__(256) void split3(
    const float* __restrict__ src, int srcLd, int K, int R,
    __nv_bfloat16* __restrict__ dst, int modeB)
{
    int idx = blockIdx.x * 256 + threadIdx.x;
    if (idx >= R * K) return;
    int r = idx / K, k = idx - r * K;
    split_one(src[(size_t)r * srcLd + k], dst, (size_t)r * (3 * K), K, k, modeB);
}

// all four weight splits fused (keeps the launch count down and puts the
// keys MMA at capture index #4)
#define E1 (DH * DIMG)            // kv_W
#define E2 (DH * DH)              // attn_Wk
#define E3 ((4 * DH) * DH)        // W_ih x-half
#define E4 (VV * DH)              // out_W
__global__ __launch_bounds__(256) void split_weights(
    const float* __restrict__ kvW, const float* __restrict__ attnWk,
    const float* __restrict__ Wih, const float* __restrict__ outW)
{
    const int total = E1 + E2 + E3 + E4;
    for (int idx = blockIdx.x * 256 + threadIdx.x; idx < total;
         idx += gridDim.x * 256) {
        if (idx < E1) {
            int r = idx / DIMG, k = idx - r * DIMG;
            split_one(kvW[(size_t)r * DIMG + k], s_kvW2,
                      (size_t)r * (3 * DIMG), DIMG, k, 1);
        } else if (idx < E1 + E2) {
            int j = idx - E1;
            int r = j / DH, k = j - r * DH;
            split_one(attnWk[(size_t)r * DH + k], s_attnWk2,
                      (size_t)r * (3 * DH), DH, k, 1);
        } else if (idx < E1 + E2 + E3) {
            int j = idx - E1 - E2;
            int r = j / DH, k = j - r * DH;
            split_one(Wih[(size_t)r * (2 * DH) + k], s_Wih2,
                      (size_t)r * (3 * DH), DH, k, 1);
        } else {
            int j = idx - E1 - E2 - E3;
            int r = j / DH, k = j - r * DH;
            split_one(outW[(size_t)r * DH + k], s_outW2,
                      (size_t)r * (3 * DH), DH, k, 1);
        }
    }
}

// embedding gather fused with split (A-mode)
__global__ __launch_bounds__(256) void gather_split(
    const int* __restrict__ tgt, const float* __restrict__ emb)
{
    int idx = blockIdx.x * 256 + threadIdx.x;
    if (idx >= BB * TT * DH) return;
    int row = idx >> 9, d = idx & 511;
    float x = emb[(size_t)tgt[row] * DH + d];
    split_one(x, s_Xemb2, (size_t)row * (3 * DH), DH, d, 0);
}

// ============================ bf16 HMMA GEMM =================================
// C[M, Nc] = A2[M, K] * B2[N, K]^T (+bias), bf16 in (3-seg split), fp32 out.
// CTA tile 128 x BN, BK=32 bf16, warp tile 64x64, mma.sync m16n8k16.
template<int BN, int NW>
__global__ __launch_bounds__(NW * 32) void gemm_mma(
    const __nv_bfloat16* __restrict__ A2, int lda,
    const __nv_bfloat16* __restrict__ B2, int ldb,
    const float* __restrict__ bias, float* __restrict__ C, int ldc,
    int Nc, int K)
{
    constexpr int BM = 128;
    constexpr int NT = NW * 32;
    constexpr int ACH = (BM * 4) / NT;   // 16B chunks per thread (A)
    constexpr int BCH = (BN * 4) / NT;
    __shared__ __nv_bfloat16 sA[BM * 40];   // rows padded to 40 elems (80B)
    __shared__ __nv_bfloat16 sB[BN * 40];

    int tid = threadIdx.x, lane = tid & 31, warp = tid >> 5;
    int wm = warp & 1, wn = warp >> 1;      // warp tile 64(m) x 64(n)
    int m0 = blockIdx.y * BM, n0 = blockIdx.x * BN;
    uint32_t sAu = smem_u32(sA), sBu = smem_u32(sB);

    float acc[4][8][4];
#pragma unroll
    for (int i = 0; i < 4; i++)
#pragma unroll
        for (int j = 0; j < 8; j++)
#pragma unroll
            for (int q = 0; q < 4; q++) acc[i][j][q] = 0.0f;

    const __nv_bfloat16* Abase = A2 + (size_t)m0 * lda;
    const __nv_bfloat16* Bbase = B2 + (size_t)n0 * ldb;
    uint4 pa[ACH], pb[BCH];

    auto ldA = [&](int s) {
#pragma unroll
        for (int i = 0; i < ACH; i++) {
            int ch = tid + i * NT, row = ch >> 2, seg = ch & 3;
            pa[i] = *reinterpret_cast<const uint4*>(
                Abase + (size_t)row * lda + s * 32 + seg * 8);
        }
    };
    auto ldB = [&](int s) {
#pragma unroll
        for (int i = 0; i < BCH; i++) {
            int ch = tid + i * NT, row = ch >> 2, seg = ch & 3;
            pb[i] = *reinterpret_cast<const uint4*>(
                Bbase + (size_t)row * ldb + s * 32 + seg * 8);
        }
    };
    auto stA = [&]() {
#pragma unroll
        for (int i = 0; i < ACH; i++) {
            int ch = tid + i * NT, row = ch >> 2, seg = ch & 3;
            *reinterpret_cast<uint4*>(sA + row * 40 + seg * 8) = pa[i];
        }
    };
    auto stB = [&]() {
#pragma unroll
        for (int i = 0; i < BCH; i++) {
            int ch = tid + i * NT, row = ch >> 2, seg = ch & 3;
            *reinterpret_cast<uint4*>(sB + row * 40 + seg * 8) = pb[i];
        }
    };
    auto compute = [&]() {
#pragma unroll
        for (int kk2 = 0; kk2 < 2; kk2++) {
            int kk = kk2 * 16;
            uint32_t a[4][4];
#pragma unroll
            for (int mi = 0; mi < 4; mi++) {
                int row = wm * 64 + mi * 16 + (lane & 15);
                int col = kk + (lane >> 4) * 8;
                ldsm_x4(a[mi][0], a[mi][1], a[mi][2], a[mi][3],
                        sAu + (uint32_t)(row * 40 + col) * 2);
            }
#pragma unroll
            for (int nj = 0; nj < 8; nj++) {
                uint32_t b[2];
                int row = wn * 64 + nj * 8 + (lane & 7);
                int col = kk + ((lane >> 3) & 1) * 8;
                ldsm_x2(b[0], b[1], sBu + (uint32_t)(row * 40 + col) * 2);
#pragma unroll
                for (int mi = 0; mi < 4; mi++) mma16816(acc[mi][nj], a[mi], b);
            }
        }
    };

    int ns = K / 32;
    ldA(0); ldB(0);
    stA(); stB();
    __syncthreads();
    for (int s = 0; s < ns; s++) {
        bool more = (s + 1 < ns);
        if (more) { ldA(s + 1); ldB(s + 1); }
        compute();
        if (more) {
            __syncthreads();
            stA(); stB();
            __syncthreads();
        }
    }

#pragma unroll
    for (int mi = 0; mi < 4; mi++) {
        int mrow = m0 + wm * 64 + mi * 16 + (lane >> 2);
#pragma unroll
        for (int half = 0; half < 2; half++) {
            float* crow = C + (size_t)(mrow + half * 8) * ldc;
#pragma unroll
            for (int nj = 0; nj < 8; nj++) {
                int gn = n0 + wn * 64 + nj * 8 + (lane & 3) * 2;
                if (gn < Nc) {
                    float2 v;
                    v.x = acc[mi][nj][half * 2 + 0] + (bias ? bias[gn] : 0.0f);
                    v.y = acc[mi][nj][half * 2 + 1] + (bias ? bias[gn + 1] : 0.0f);
                    *reinterpret_cast<float2*>(crow + gn) = v;
                }
            }
        }
    }
}

// ============================ skinny GEMM chunk ==============================
__device__ __forceinline__ void skinny_chunk(
    const float* __restrict__ A, int lda,
    const float* __restrict__ B, int ldb,
    float acc[8], float* sA, float* sB)
{
    int tid = threadIdx.x;
    __syncthreads();
#pragma unroll
    for (int i = tid; i < 32 * 64; i += 256) {
        int b = i >> 6, k = i & 63;
        sA[k * 36 + b] = A[(size_t)b * lda + k];
    }
#pragma unroll
    for (int i = tid; i < 64 * 64; i += 256) {
        int n = i >> 6, k = i & 63;
        sB[k * 65 + n] = B[(size_t)n * ldb + k];
    }
    __syncthreads();
    int nl = tid & 63, bq = tid >> 6;
#pragma unroll 8
    for (int k = 0; k < 64; k++) {
        float w = sB[k * 65 + nl];
        const float4* ap = reinterpret_cast<const float4*>(&sA[k * 36 + bq * 8]);
        float4 a0 = ap[0], a1 = ap[1];
        acc[0] = fmaf(a0.x, w, acc[0]); acc[1] = fmaf(a0.y, w, acc[1]);
        acc[2] = fmaf(a0.z, w, acc[2]); acc[3] = fmaf(a0.w, w, acc[3]);
        acc[4] = fmaf(a1.x, w, acc[4]); acc[5] = fmaf(a1.y, w, acc[5]);
        acc[6] = fmaf(a1.z, w, acc[6]); acc[7] = fmaf(a1.w, w, acc[7]);
    }
}

// ============================ persistent recurrence ==========================
__global__ __launch_bounds__(NTHR) void recurrence(
    const float* __restrict__ cls,
    const float* __restrict__ ih_W, const float* __restrict__ ih_b,
    const float* __restrict__ ic_W, const float* __restrict__ ic_b,
    const float* __restrict__ attn_Wh, const float* __restrict__ attn_v,
    const float* __restrict__ W_ih, const float* __restrict__ W_hh,
    const float* __restrict__ b_ih, const float* __restrict__ b_hh,
    const float* __restrict__ lnw, const float* __restrict__ lnb)
{
    __shared__ float sh[64 * 36 + 64 * 65];
    float* sA = sh;
    float* sB = sh + 64 * 36;
    int tid = threadIdx.x;
    int cta = blockIdx.x;
    int nl = tid & 63, bq = tid >> 6;

    // prologue: h0 / c0
    for (int task = cta; task < 16; task += NCTA) {
        int mat = task >> 3;
        int n0 = (task & 7) * 64;
        const float* W = mat ? ic_W : ih_W;
        const float* bias = mat ? ic_b : ih_b;
        float* dst = mat ? g_c : g_h;
        float acc[8] = {0, 0, 0, 0, 0, 0, 0, 0};
        for (int kc = 0; kc < 12; kc++)
            skinny_chunk(cls + kc * 64, DIMG, W + (size_t)n0 * DIMG + kc * 64, DIMG,
                         acc, sA, sB);
        float bv = bias[n0 + nl];
#pragma unroll
        for (int j = 0; j < 8; j++)
            dst[(size_t)(bq * 8 + j) * DH + n0 + nl] = acc[j] + bv;
    }
    grid_barrier();

    for (int t = 0; t < TT; t++) {
        // P1: hWh partials = h @ attn_Wh^T (64 tasks)
        for (int task = cta; task < 64; task += NCTA) {
            int kslot = task >> 3, n0 = (task & 7) * 64, k0 = kslot * 64;
            float acc[8] = {0, 0, 0, 0, 0, 0, 0, 0};
            skinny_chunk(g_h + k0, DH, attn_Wh + (size_t)n0 * DH + k0, DH,
                         acc, sA, sB);
#pragma unroll
            for (int j = 0; j < 8; j++)
                g_hwh_p[((size_t)kslot * BB + bq * 8 + j) * DH + n0 + nl] = acc[j];
        }
        grid_barrier();

        // P2: scores (128 tasks) — FMA-only tanh
        {
            float* hwh = sh;
            float* vsm = sh + 512;
            for (int task = cta; task < 128; task += NCTA) {
                int b = task >> 2, n0 = (task & 3) * 49;
                __syncthreads();
#pragma unroll
                for (int d = tid; d < DH; d += 256) {
                    float s = 0.0f;
#pragma unroll
                    for (int s8 = 0; s8 < 8; s8++)
                        s += g_hwh_p[((size_t)s8 * BB + b) * DH + d];
                    hwh[d] = s;
                    vsm[d] = attn_v[d];
                }
                __syncthreads();
                int w = tid >> 5, l = tid & 31;
                for (int n = n0 + w; n < n0 + 49; n += 8) {
                    const float* wk = &g_Wk[((size_t)b * NN + n) * DH];
                    float e = 0.0f;
#pragma unroll 4
                    for (int k = l; k < DH; k += 32)
                        e = fmaf(tanh_fma(hwh[k] + wk[k]), vsm[k], e);
                    e = warp_sum(e);
                    if (l == 0) g_sc[b * 256 + n] = e;
                }
            }
        }
        grid_barrier();

        // P3: softmax + ctx (64 tasks), 7 independent FMA chains
        {
            float* alpha = sh;
            float* red = sh + 256;
            for (int task = cta; task < 64; task += NCTA) {
                int b = task >> 1, d0 = (task & 1) * 256;
                __syncthreads();
                float s = (tid < NN) ? g_sc[b * 256 + tid] : -1e30f;
                float m = block_max256(s, red);
                float ex = (tid < NN) ? expf(s - m) : 0.0f;
                alpha[tid] = ex;
                float ssum = block_sum256(ex, red);
                float inv = 1.0f / ssum;
                int d = d0 + tid;
                const float* kb = &g_keys[(size_t)b * NN * DH + d];
                float a0 = 0.f, a1 = 0.f, a2 = 0.f, a3 = 0.f;
                float a4 = 0.f, a5 = 0.f, a6 = 0.f;
                for (int n = 0; n < NN; n += 7) {
                    a0 = fmaf(alpha[n + 0], kb[(size_t)(n + 0) * DH], a0);
                    a1 = fmaf(alpha[n + 1], kb[(size_t)(n + 1) * DH], a1);
                    a2 = fmaf(alpha[n + 2], kb[(size_t)(n + 2) * DH], a2);
                    a3 = fmaf(alpha[n + 3], kb[(size_t)(n + 3) * DH], a3);
                    a4 = fmaf(alpha[n + 4], kb[(size_t)(n + 4) * DH], a4);
                    a5 = fmaf(alpha[n + 5], kb[(size_t)(n + 5) * DH], a5);
                    a6 = fmaf(alpha[n + 6], kb[(size_t)(n + 6) * DH], a6);
                }
                float ctx = ((a0 + a1) + (a2 + a3)) + ((a4 + a5) + a6);
                g_ctx[b * DH + d] = ctx * inv;
            }
        }
        grid_barrier();

        // P4: gate partials (128 tasks)
        for (int task = cta; task < 128; task += NCTA) {
            int kslot = task >> 5, n0 = (task & 31) * 64, k0 = kslot * 256;
            float acc[8] = {0, 0, 0, 0, 0, 0, 0, 0};
            for (int kc = 0; kc < 4; kc++) {
                int kk = k0 + kc * 64;
                if (kk < 512)
                    skinny_chunk(g_ctx + kk, DH,
                                 W_ih + (size_t)n0 * (2 * DH) + DH + kk, 2 * DH,
                                 acc, sA, sB);
                else
                    skinny_chunk(g_h + (kk - 512), DH,
                                 W_hh + (size_t)n0 * DH + (kk - 512), DH,
                                 acc, sA, sB);
            }
#pragma unroll
            for (int j = 0; j < 8; j++)
                g_pg[((size_t)kslot * BB + bq * 8 + j) * (4 * DH) + n0 + nl] = acc[j];
        }
        grid_barrier();

        // P5: cell + layernorm (32 tasks)
        {
            float* red = sh;
            for (int task = cta; task < BB; task += NCTA) {
                int b = task;
                size_t xrow = ((size_t)b * TT + t) * (4 * DH);
                float hr[2], cn[2];
#pragma unroll
                for (int half = 0; half < 2; half++) {
                    int d = tid + half * 256;
                    float gi = 0.f, gf = 0.f, gg = 0.f, go = 0.f;
#pragma unroll
                    for (int s = 0; s < 4; s++) {
                        const float* p = g_pg + ((size_t)s * BB + b) * (4 * DH);
                        gi += p[d]; gf += p[DH + d];
                        gg += p[2 * DH + d]; go += p[3 * DH + d];
                    }
                    const float* xp = g_X + xrow;
                    gi += xp[d] + b_ih[d] + b_hh[d];
                    gf += xp[DH + d] + b_ih[DH + d] + b_hh[DH + d];
                    gg += xp[2 * DH + d] + b_ih[2 * DH + d] + b_hh[2 * DH + d];
                    go += xp[3 * DH + d] + b_ih[3 * DH + d] + b_hh[3 * DH + d];
                    float c = g_c[b * DH + d];
                    cn[half] = sigmoidf_acc(gf) * c + sigmoidf_acc(gi) * tanh_fma(gg);
                    hr[half] = sigmoidf_acc(go) * tanh_fma(cn[half]);
                }
                __syncthreads();
                float mu = block_sum256(hr[0] + hr[1], red) * (1.0f / DH);
                float va = block_sum256(hr[0] * hr[0] + hr[1] * hr[1], red) * (1.0f / DH)
                           - mu * mu;
                float rstd = rsqrtf(va + 1e-5f);
#pragma unroll
                for (int half = 0; half < 2; half++) {
                    int d = tid + half * 256;
                    float hn = (hr[half] - mu) * rstd * lnw[d] + lnb[d];
                    g_c[b * DH + d] = cn[half];
                    g_h[b * DH + d] = hn;
                    g_H[((size_t)b * TT + t) * DH + d] = hn;
                }
            }
        }
        grid_barrier();
    }
}

// ============================ launcher =======================================
extern "C" void kernel_launch(void* const* d_in, const int* in_sizes, int n_in,
                              void* d_out, int out_size)
{
    (void)in_sizes; (void)n_in; (void)out_size;
    const float* patches = (const float*)d_in[0];
    const float* cls     = (const float*)d_in[1];
    const int*   tgt     = (const int*)  d_in[2];
    const float* emb     = (const float*)d_in[3];
    const float* kv_W    = (const float*)d_in[4];
    const float* kv_b    = (const float*)d_in[5];
    const float* ih_W    = (const float*)d_in[6];
    const float* ih_b    = (const float*)d_in[7];
    const float* ic_W    = (const float*)d_in[8];
    const float* ic_b    = (const float*)d_in[9];
    const float* attn_Wh = (const float*)d_in[10];
    const float* attn_Wk = (const float*)d_in[11];
    const float* attn_v  = (const float*)d_in[12];
    const float* W_ih    = (const float*)d_in[13];
    const float* W_hh    = (const float*)d_in[14];
    const float* b_ih    = (const float*)d_in[15];
    const float* b_hh    = (const float*)d_in[16];
    const float* ln_w    = (const float*)d_in[17];
    const float* ln_b    = (const float*)d_in[18];
    const float* out_W   = (const float*)d_in[19];
    const float* out_b   = (const float*)d_in[20];
    float* out = (float*)d_out;

    float *p_keys, *p_Wk, *p_X, *p_H;
    cudaGetSymbolAddress((void**)&p_keys, g_keys);
    cudaGetSymbolAddress((void**)&p_Wk,   g_Wk);
    cudaGetSymbolAddress((void**)&p_X,    g_X);
    cudaGetSymbolAddress((void**)&p_H,    g_H);
    __nv_bfloat16 *p_patches2, *p_kvW2, *p_keys2, *p_attnWk2, *p_Xemb2,
                  *p_Wih2, *p_H2, *p_outW2;
    cudaGetSymbolAddress((void**)&p_patches2, s_patches2);
    cudaGetSymbolAddress((void**)&p_kvW2,     s_kvW2);
    cudaGetSymbolAddress((void**)&p_keys2,    s_keys2);
    cudaGetSymbolAddress((void**)&p_attnWk2,  s_attnWk2);
    cudaGetSymbolAddress((void**)&p_Xemb2,    s_Xemb2);
    cudaGetSymbolAddress((void**)&p_Wih2,     s_Wih2);
    cudaGetSymbolAddress((void**)&p_H2,       s_H2);
    cudaGetSymbolAddress((void**)&p_outW2,    s_outW2);

    auto blocks = [](long n) { return (int)((n + 255) / 256); };

    // 1: all weight splits fused
    split_weights<<<8192, 256>>>(kv_W, attn_Wk, W_ih, out_W);
    // 2: embedding gather + split
    gather_split<<<blocks((long)BB * TT * DH), 256>>>(tgt, emb);
    // 3: patches split
    split3<<<blocks((long)BB * NN * DIMG), 256>>>(patches, DIMG, DIMG, BB * NN,
                                                  p_patches2, 0);
    // 4: keys = patches @ kv_W^T + kv_b  [6272, 512], K' = 2304  (HMMA)
    gemm_mma<128, 4><<<dim3(DH / 128, (BB * NN) / 128), 128>>>(
        p_patches2, 3 * DIMG, p_kvW2, 3 * DIMG, kv_b, p_keys, DH, DH, 3 * DIMG);
    // 5: keys split
    split3<<<blocks((long)BB * NN * DH), 256>>>(p_keys, DH, DH, BB * NN, p_keys2, 0);
    // 6: Wk_keys = keys @ attn_Wk^T  [6272, 512], K' = 1536
    gemm_mma<128, 4><<<dim3(DH / 128, (BB * NN) / 128), 128>>>(
        p_keys2, 3 * DH, p_attnWk2, 3 * DH, nullptr, p_Wk, DH, DH, 3 * DH);
    // 7: X = Xemb @ W_ih[:, :512]^T  [4096, 2048], K' = 1536
    gemm_mma<256, 8><<<dim3((4 * DH) / 256, (BB * TT) / 128), 256>>>(
        p_Xemb2, 3 * DH, p_Wih2, 3 * DH, nullptr, p_X, 4 * DH, 4 * DH, 3 * DH);
    // 8: persistent recurrence
    recurrence<<<NCTA, NTHR>>>(cls, ih_W, ih_b, ic_W, ic_b,
                               attn_Wh, attn_v, W_ih, W_hh, b_ih, b_hh,
                               ln_w, ln_b);
    // 9: H split
    split3<<<blocks((long)BB * TT * DH), 256>>>(p_H, DH, DH, BB * TT, p_H2, 0);
    // 10: logits = H @ out_W^T + out_b  [4096, 10000], K' = 1536
    gemm_mma<256, 8><<<dim3(VPAD / 256, (BB * TT) / 128), 256>>>(
        p_H2, 3 * DH, p_outW2, 3 * DH, out_b, out, VV, VV, 3 * DH);
}